// round 17
// baseline (speedup 1.0000x reference)
#include <cuda_runtime.h>
#include <cuda_fp16.h>
#include <cstdint>
#include <math.h>

// Problem constants
#define BATCH 4
#define SEQ   1024
#define DIM   1024
#define HEADS 16
#define HSZ   64
#define SCALE_F 0.125f
#define BD (SEQ * DIM)

// ---------------------------------------------------------------------------
// Scratch (__device__ globals; no allocations allowed). fp16 single copies.
// ---------------------------------------------------------------------------
__device__ __half g_Q [BATCH * BD];
__device__ __half g_K [BATCH * BD];
__device__ __half g_V [BATCH * BD];
__device__ __half g_C [BATCH * BD];
__device__ __half g_aK[BATCH * BD];
__device__ __half g_aV[BATCH * BD];
__device__ __half g_aQ[BATCH * BD];
__device__ __half g_wK[DIM * DIM];
__device__ __half g_wV[DIM * DIM];
__device__ __half g_wQ[DIM * DIM];
__device__ __half g_wO[DIM * DIM];

// ===========================================================================
// PTX helpers (family-agnostic sm_80+; ptxas target is compute_103 w/o 'a')
// ===========================================================================
__device__ __forceinline__ uint32_t smem_u32(const void* p) {
    uint32_t a;
    asm("{ .reg .u64 t; cvta.to.shared.u64 t, %1; cvt.u32.u64 %0, t; }"
        : "=r"(a) : "l"(p));
    return a;
}
__device__ __forceinline__ void cpa16(uint32_t dst, const void* src) {
    asm volatile("cp.async.cg.shared.global [%0], [%1], 16;"
                 :: "r"(dst), "l"(src) : "memory");
}
#define CPA_COMMIT() asm volatile("cp.async.commit_group;" ::: "memory")
#define CPA_WAIT(n)  asm volatile("cp.async.wait_group %0;" :: "n"(n) : "memory")

__device__ __forceinline__ void ldsm4(uint32_t (&r)[4], uint32_t a) {
    asm volatile("ldmatrix.sync.aligned.m8n8.x4.shared.b16 {%0,%1,%2,%3}, [%4];"
                 : "=r"(r[0]), "=r"(r[1]), "=r"(r[2]), "=r"(r[3]) : "r"(a));
}
__device__ __forceinline__ void ldsm4t(uint32_t (&r)[4], uint32_t a) {
    asm volatile("ldmatrix.sync.aligned.m8n8.x4.trans.shared.b16 {%0,%1,%2,%3}, [%4];"
                 : "=r"(r[0]), "=r"(r[1]), "=r"(r[2]), "=r"(r[3]) : "r"(a));
}
// fp16 inputs, fp32 accumulate
__device__ __forceinline__ void mma16816(float (&d)[4], const uint32_t (&a)[4],
                                         uint32_t b0, uint32_t b1) {
    asm volatile(
        "mma.sync.aligned.m16n8k16.row.col.f32.f16.f16.f32 "
        "{%0,%1,%2,%3}, {%4,%5,%6,%7}, {%8,%9}, {%0,%1,%2,%3};"
        : "+f"(d[0]), "+f"(d[1]), "+f"(d[2]), "+f"(d[3])
        : "r"(a[0]), "r"(a[1]), "r"(a[2]), "r"(a[3]), "r"(b0), "r"(b1));
}
__device__ __forceinline__ uint32_t packh2(float x, float y) {
    __half2 t = __floats2half2_rn(x, y);
    return *reinterpret_cast<uint32_t*>(&t);
}

// ===========================================================================
// convert kernel: fp32 -> fp16
// ===========================================================================
__global__ __launch_bounds__(256)
void cvt_kernel(const float4* __restrict__ in, uint2* __restrict__ out, int n4)
{
    int i = blockIdx.x * 256 + threadIdx.x;
    if (i >= n4) return;
    float4 v = in[i];
    uint2 o;
    o.x = packh2(v.x, v.y);
    o.y = packh2(v.z, v.w);
    out[i] = o;
}

// ===========================================================================
// Single-pass fp16 GEMM:  C[.,1024] = A @ W (+bias, *scale)
// CTA tile 128x128, 512 threads (16 warps, 32x32 warp tiles), K-chunk 64,
// 3-stage ring, 1 sync/iter, 2 CTAs/SM -> 8 warps per SMSP (latency hiding).
// Output: fp32 (Cf != null) or fp16 (outH).
// ===========================================================================
// stage: A 128 rows x 144B = 18432 | B 64 rows x 272B = 17408
#define G_Bo 18432
#define G_STAGE 35840
#define G_SMEM (3 * G_STAGE)   // 107520 -> 2 CTAs/SM

__global__ __launch_bounds__(512, 2)
void gemm_mma_kernel(const __half* __restrict__ A,
                     const __half* __restrict__ B,
                     const float* __restrict__ bias,
                     float scale, int m_off,
                     float* __restrict__ Cf,
                     __half* __restrict__ outH)
{
    extern __shared__ __align__(128) char smem[];
    const uint32_t sb = smem_u32(smem);
    const int tid  = threadIdx.x;
    const int lane = tid & 31;
    const int wid  = tid >> 5;
    const int warp_m = wid & 3;    // 4 m-groups of 32 rows
    const int warp_n = wid >> 2;   // 4 n-groups of 32 cols
    const int m0 = blockIdx.y * 128 + m_off;
    const int n0 = blockIdx.x * 128;

    float acc[2][4][4];
#pragma unroll
    for (int mt = 0; mt < 2; mt++)
#pragma unroll
        for (int nt = 0; nt < 4; nt++)
#pragma unroll
            for (int j = 0; j < 4; j++) acc[mt][nt][j] = 0.0f;

    auto load_chunk = [&](int c, int stage) {
        const int k0 = c * 64;
        const uint32_t base = sb + stage * G_STAGE;
        // A: 128 rows x 8 x 16B segs = 1024 slots (512 thr x 2)
#pragma unroll
        for (int u = 0; u < 2; u++) {
            int idx = tid + u * 512;
            int r = idx >> 3, seg = idx & 7;
            cpa16(base + r * 144 + seg * 16,
                  A + (size_t)(m0 + r) * 1024 + k0 + seg * 8);
        }
        // B: 64 rows x 16 x 16B segs = 1024 slots
#pragma unroll
        for (int u = 0; u < 2; u++) {
            int idx = tid + u * 512;
            int row = idx >> 4, seg = idx & 15;
            cpa16(base + G_Bo + row * 272 + seg * 16,
                  B + (size_t)(k0 + row) * 1024 + n0 + seg * 8);
        }
    };

    load_chunk(0, 0); CPA_COMMIT();
    load_chunk(1, 1); CPA_COMMIT();

    const uint32_t a_off = (uint32_t)(warp_m * 32 + (lane & 15)) * 144 + (lane >> 4) * 16;
    const int quad = lane >> 3;
    const uint32_t trow8 = (quad & 1) * 8 + (lane & 7);
    const uint32_t b_colb = (uint32_t)(warp_n * 32 + (quad >> 1) * 8) * 2;

    int s_cur = 0;
    for (int c = 0; c < 16; c++) {
        CPA_WAIT(1);
        __syncthreads();
        int s_nxt = s_cur + 2; if (s_nxt >= 3) s_nxt -= 3;
        if (c + 2 < 16) load_chunk(c + 2, s_nxt);
        CPA_COMMIT();

        const uint32_t base = sb + s_cur * G_STAGE;
#pragma unroll
        for (int ks = 0; ks < 4; ks++) {
            uint32_t a4[2][4];
#pragma unroll
            for (int mt = 0; mt < 2; mt++)
                ldsm4(a4[mt], base + a_off + mt * 16 * 144 + ks * 32);
            uint32_t bf[4][2];
            const uint32_t brow = (uint32_t)(ks * 16) + trow8;
#pragma unroll
            for (int np = 0; np < 2; np++) {
                uint32_t r[4];
                ldsm4t(r, base + G_Bo + brow * 272 + b_colb + np * 32);
                bf[np * 2][0] = r[0]; bf[np * 2][1] = r[1];
                bf[np * 2 + 1][0] = r[2]; bf[np * 2 + 1][1] = r[3];
            }
#pragma unroll
            for (int mt = 0; mt < 2; mt++)
#pragma unroll
                for (int nt = 0; nt < 4; nt++)
                    mma16816(acc[mt][nt], a4[mt], bf[nt][0], bf[nt][1]);
        }
        s_cur += 1; if (s_cur >= 3) s_cur -= 3;
    }

    // epilogue
#pragma unroll
    for (int mt = 0; mt < 2; mt++) {
        int row = m0 + warp_m * 32 + mt * 16 + (lane >> 2);
#pragma unroll
        for (int nt = 0; nt < 4; nt++) {
            int col = n0 + warp_n * 32 + nt * 8 + (lane & 3) * 2;
            float b0 = bias[col], b1 = bias[col + 1];
            float v00 = (acc[mt][nt][0] + b0) * scale;
            float v01 = (acc[mt][nt][1] + b1) * scale;
            float v10 = (acc[mt][nt][2] + b0) * scale;
            float v11 = (acc[mt][nt][3] + b1) * scale;
            size_t i0 = (size_t)row * 1024 + col;
            size_t i1 = (size_t)(row + 8) * 1024 + col;
            if (Cf) {
                *reinterpret_cast<float2*>(Cf + i0) = make_float2(v00, v01);
                *reinterpret_cast<float2*>(Cf + i1) = make_float2(v10, v11);
            } else {
                *reinterpret_cast<uint32_t*>(outH + i0) = packh2(v00, v01);
                *reinterpret_cast<uint32_t*>(outH + i1) = packh2(v10, v11);
            }
        }
    }
}

// ===========================================================================
// fp16 flash attention (unchanged from R16).  3-stage KV ring, 1 sync/tile.
// ===========================================================================
#define ATT_ST_OFF 16384
#define ATT_ST_STRIDE 16384
#define ATT_SMEM (16384 + 3 * ATT_ST_STRIDE)   // 65536
#define SWZA(row, ch) ((uint32_t)(row) * 128 + ((((uint32_t)(ch)) ^ ((row) & 7)) * 16))

__global__ __launch_bounds__(256, 2)
void attn_mma_kernel(const __half* __restrict__ Q,
                     const __half* __restrict__ K,
                     const __half* __restrict__ V,
                     __half* __restrict__ C,
                     int bh_off)
{
    extern __shared__ __align__(128) char smem[];
    const uint32_t sb = smem_u32(smem);
    const int tid  = threadIdx.x;
    const int lane = tid & 31;
    const int wid  = tid >> 5;
    const int bh = blockIdx.y + bh_off;
    const int b  = bh >> 4;
    const int h  = bh & 15;
    const int q0 = blockIdx.x * 128;
    const size_t bbase = (size_t)b * BD;
    const int quad = lane >> 3;

#pragma unroll
    for (int u = 0; u < 4; u++) {
        int idx = tid + u * 256;
        int row = idx >> 3, ch = idx & 7;
        size_t off = bbase + h * 65536 + (size_t)(q0 + row) * 64 + ch * 8;
        cpa16(sb + SWZA(row, ch), Q + off);
    }
    CPA_COMMIT();

    auto load_kv = [&](int kt, int s) {
        const int k0 = kt * 64;
        const uint32_t stg = sb + ATT_ST_OFF + s * ATT_ST_STRIDE;
#pragma unroll
        for (int u = 0; u < 2; u++) {
            int idx = tid + u * 256;
            int row = idx >> 3, ch = idx & 7;
            uint32_t dst = SWZA(row, ch);
            size_t koff = bbase + (size_t)(h * 64 + row) * 1024 + k0 + ch * 8;
            cpa16(stg + dst, K + koff);
            size_t voff = bbase + h * 65536 + (size_t)(k0 + row) * 64 + ch * 8;
            cpa16(stg + 8192 + dst, V + voff);
        }
    };

    load_kv(0, 0); CPA_COMMIT();
    load_kv(1, 1); CPA_COMMIT();

    float O[8][4];
#pragma unroll
    for (int nt = 0; nt < 8; nt++)
#pragma unroll
        for (int j = 0; j < 4; j++) O[nt][j] = 0.0f;
    float m0r = -3.0e38f, m1r = -3.0e38f, l0r = 0.0f, l1r = 0.0f;

    const int qrow = wid * 16 + (lane & 15);
    const int trow8 = (quad & 1) * 8 + (lane & 7);
    const int tch   = quad >> 1;

    int s_cur = 0;
    for (int kt = 0; kt < 16; kt++) {
        CPA_WAIT(1);
        __syncthreads();
        int s_nxt = s_cur + 2; if (s_nxt >= 3) s_nxt -= 3;
        if (kt + 2 < 16) load_kv(kt + 2, s_nxt);
        CPA_COMMIT();

        const uint32_t stg = sb + ATT_ST_OFF + s_cur * ATT_ST_STRIDE;
        const uint32_t sK = stg, sV = stg + 8192;

        float S[8][4];
#pragma unroll
        for (int nt = 0; nt < 8; nt++)
#pragma unroll
            for (int j = 0; j < 4; j++) S[nt][j] = 0.0f;

#pragma unroll
        for (int ks = 0; ks < 4; ks++) {
            uint32_t q4[4];
            ldsm4(q4, sb + SWZA(qrow, ks * 2 + (lane >> 4)));
            int krow = ks * 16 + trow8;
#pragma unroll
            for (int p = 0; p < 4; p++) {
                uint32_t k4[4];
                ldsm4t(k4, sK + SWZA(krow, p * 2 + tch));
                mma16816(S[2 * p],     q4, k4[0], k4[1]);
                mma16816(S[2 * p + 1], q4, k4[2], k4[3]);
            }
        }

        float mx0 = S[0][0], mx1 = S[0][2];
#pragma unroll
        for (int nt = 0; nt < 8; nt++) {
            mx0 = fmaxf(mx0, fmaxf(S[nt][0], S[nt][1]));
            mx1 = fmaxf(mx1, fmaxf(S[nt][2], S[nt][3]));
        }
        mx0 = fmaxf(mx0, __shfl_xor_sync(0xffffffffu, mx0, 1));
        mx0 = fmaxf(mx0, __shfl_xor_sync(0xffffffffu, mx0, 2));
        mx1 = fmaxf(mx1, __shfl_xor_sync(0xffffffffu, mx1, 1));
        mx1 = fmaxf(mx1, __shfl_xor_sync(0xffffffffu, mx1, 2));

        float mn0 = fmaxf(m0r, mx0);
        float mn1 = fmaxf(m1r, mx1);
        float c0 = __expf(m0r - mn0);
        float c1 = __expf(m1r - mn1);
        m0r = mn0; m1r = mn1;

        float rs0 = 0.0f, rs1 = 0.0f;
#pragma unroll
        for (int nt = 0; nt < 8; nt++) {
            S[nt][0] = __expf(S[nt][0] - mn0);
            S[nt][1] = __expf(S[nt][1] - mn0);
            S[nt][2] = __expf(S[nt][2] - mn1);
            S[nt][3] = __expf(S[nt][3] - mn1);
            rs0 += S[nt][0] + S[nt][1];
            rs1 += S[nt][2] + S[nt][3];
        }
        rs0 += __shfl_xor_sync(0xffffffffu, rs0, 1);
        rs0 += __shfl_xor_sync(0xffffffffu, rs0, 2);
        rs1 += __shfl_xor_sync(0xffffffffu, rs1, 1);
        rs1 += __shfl_xor_sync(0xffffffffu, rs1, 2);
        l0r = l0r * c0 + rs0;
        l1r = l1r * c1 + rs1;
#pragma unroll
        for (int nt = 0; nt < 8; nt++) {
            O[nt][0] *= c0; O[nt][1] *= c0;
            O[nt][2] *= c1; O[nt][3] *= c1;
        }

#pragma unroll
        for (int ks = 0; ks < 4; ks++) {
            uint32_t ph[4];
            ph[0] = packh2(S[2 * ks][0],     S[2 * ks][1]);
            ph[1] = packh2(S[2 * ks][2],     S[2 * ks][3]);
            ph[2] = packh2(S[2 * ks + 1][0], S[2 * ks + 1][1]);
            ph[3] = packh2(S[2 * ks + 1][2], S[2 * ks + 1][3]);
            int vrow = ks * 16 + trow8;
#pragma unroll
            for (int p = 0; p < 4; p++) {
                uint32_t v4[4];
                ldsm4t(v4, sV + SWZA(vrow, p * 2 + tch));
                mma16816(O[2 * p],     ph, v4[0], v4[1]);
                mma16816(O[2 * p + 1], ph, v4[2], v4[3]);
            }
        }
        s_cur += 1; if (s_cur >= 3) s_cur -= 3;
    }

    float inv0 = 1.0f / l0r;
    float inv1 = 1.0f / l1r;
    int r0 = q0 + wid * 16 + (lane >> 2);
    int r1 = r0 + 8;
#pragma unroll
    for (int nt = 0; nt < 8; nt++) {
        int col = h * 64 + nt * 8 + (lane & 3) * 2;
        size_t i0 = (size_t)(b * 1024 + r0) * 1024 + col;
        size_t i1 = (size_t)(b * 1024 + r1) * 1024 + col;
        *reinterpret_cast<uint32_t*>(C + i0) =
            packh2(O[nt][0] * inv0, O[nt][1] * inv0);
        *reinterpret_cast<uint32_t*>(C + i1) =
            packh2(O[nt][2] * inv1, O[nt][3] * inv1);
    }
}

// ---------------------------------------------------------------------------
// Launch.  Inputs: k, v, q, mask, Wk, bk, Wv, bv, Wq, bq, Wo, bo
// ---------------------------------------------------------------------------
extern "C" void kernel_launch(void* const* d_in, const int* in_sizes, int n_in,
                              void* d_out, int out_size)
{
    const float* k_in = (const float*)d_in[0];
    const float* v_in = (const float*)d_in[1];
    const float* q_in = (const float*)d_in[2];
    const float* Wk = (const float*)d_in[4];
    const float* bk = (const float*)d_in[5];
    const float* Wv = (const float*)d_in[6];
    const float* bv = (const float*)d_in[7];
    const float* Wq = (const float*)d_in[8];
    const float* bq = (const float*)d_in[9];
    const float* Wo = (const float*)d_in[10];
    const float* bo = (const float*)d_in[11];
    float* out = (float*)d_out;

    __half *Qp, *Kp, *Vp, *Cp, *aK, *aV, *aQ, *wK, *wV, *wQ, *wO;
    cudaGetSymbolAddress((void**)&Qp, g_Q);
    cudaGetSymbolAddress((void**)&Kp, g_K);
    cudaGetSymbolAddress((void**)&Vp, g_V);
    cudaGetSymbolAddress((void**)&Cp, g_C);
    cudaGetSymbolAddress((void**)&aK, g_aK);
    cudaGetSymbolAddress((void**)&aV, g_aV);
    cudaGetSymbolAddress((void**)&aQ, g_aQ);
    cudaGetSymbolAddress((void**)&wK, g_wK);
    cudaGetSymbolAddress((void**)&wV, g_wV);
    cudaGetSymbolAddress((void**)&wQ, g_wQ);
    cudaGetSymbolAddress((void**)&wO, g_wO);

    cudaFuncSetAttribute(gemm_mma_kernel,
                         cudaFuncAttributeMaxDynamicSharedMemorySize, G_SMEM);
    cudaFuncSetAttribute(attn_mma_kernel,
                         cudaFuncAttributeMaxDynamicSharedMemorySize, ATT_SMEM);

    const int nW4 = (DIM * DIM) / 4;       // 262144
    const int nA4 = (BATCH * BD) / 4;      // 1048576
    dim3 pgrid(DIM / 128, (BATCH * SEQ) / 128);   // (8, 32)
    dim3 hgrid(DIM / 128, (BATCH * SEQ) / 256);   // (8, 16) half-M

    cudaStream_t s1, s2, s3;
    cudaStreamCreateWithFlags(&s1, cudaStreamNonBlocking);
    cudaStreamCreateWithFlags(&s2, cudaStreamNonBlocking);
    cudaStreamCreateWithFlags(&s3, cudaStreamNonBlocking);
    cudaEvent_t ef, e1, e2, e3, eJ, eB;
    cudaEventCreateWithFlags(&ef, cudaEventDisableTiming);
    cudaEventCreateWithFlags(&e1, cudaEventDisableTiming);
    cudaEventCreateWithFlags(&e2, cudaEventDisableTiming);
    cudaEventCreateWithFlags(&e3, cudaEventDisableTiming);
    cudaEventCreateWithFlags(&eJ, cudaEventDisableTiming);
    cudaEventCreateWithFlags(&eB, cudaEventDisableTiming);

    cudaEventRecord(ef, 0);
    cudaStreamWaitEvent(s1, ef, 0);
    cudaStreamWaitEvent(s2, ef, 0);
    cudaStreamWaitEvent(s3, ef, 0);

    // K chain (stream 0)
    cvt_kernel<<<nW4 / 256, 256>>>((const float4*)Wk, (uint2*)wK, nW4);
    cvt_kernel<<<nA4 / 256, 256>>>((const float4*)k_in, (uint2*)aK, nA4);
    gemm_mma_kernel<<<pgrid, 512, G_SMEM>>>(aK, wK, bk, 1.0f, 0, nullptr, Kp);
    // V chain (s1)
    cvt_kernel<<<nW4 / 256, 256, 0, s1>>>((const float4*)Wv, (uint2*)wV, nW4);
    cvt_kernel<<<nA4 / 256, 256, 0, s1>>>((const float4*)v_in, (uint2*)aV, nA4);
    gemm_mma_kernel<<<pgrid, 512, G_SMEM, s1>>>(aV, wV, bv, 1.0f, 0, nullptr, Vp);
    cudaEventRecord(e1, s1);
    // Q chain (s2), softmax scale folded into epilogue
    cvt_kernel<<<nW4 / 256, 256, 0, s2>>>((const float4*)Wq, (uint2*)wQ, nW4);
    cvt_kernel<<<nA4 / 256, 256, 0, s2>>>((const float4*)q_in, (uint2*)aQ, nA4);
    gemm_mma_kernel<<<pgrid, 512, G_SMEM, s2>>>(aQ, wQ, bq, SCALE_F, 0, nullptr, Qp);
    cudaEventRecord(e2, s2);
    // Wo convert (s3)
    cvt_kernel<<<nW4 / 256, 256, 0, s3>>>((const float4*)Wo, (uint2*)wO, nW4);
    cudaEventRecord(e3, s3);

    // join
    cudaStreamWaitEvent(0, e1, 0);
    cudaStreamWaitEvent(0, e2, 0);
    cudaStreamWaitEvent(0, e3, 0);
    cudaEventRecord(eJ, 0);
    cudaStreamWaitEvent(s1, eJ, 0);

    // pipelined attention + output GEMM (batch halves on two streams)
    attn_mma_kernel<<<dim3(8, 32), 256, ATT_SMEM>>>(Qp, Kp, Vp, Cp, 0);
    gemm_mma_kernel<<<hgrid, 512, G_SMEM>>>(Cp, wO, bo, 1.0f, 0, out, nullptr);

    attn_mma_kernel<<<dim3(8, 32), 256, ATT_SMEM, s1>>>(Qp, Kp, Vp, Cp, 32);
    gemm_mma_kernel<<<hgrid, 512, G_SMEM, s1>>>(Cp, wO, bo, 1.0f, 2048, out, nullptr);
    cudaEventRecord(eB, s1);
    cudaStreamWaitEvent(0, eB, 0);

    cudaEventDestroy(ef);
    cudaEventDestroy(e1);
    cudaEventDestroy(e2);
    cudaEventDestroy(e3);
    cudaEventDestroy(eJ);
    cudaEventDestroy(eB);
    cudaStreamDestroy(s1);
    cudaStreamDestroy(s2);
    cudaStreamDestroy(s3);
}